// round 1
// baseline (speedup 1.0000x reference)
#include <cuda_runtime.h>

#define N_USERS 50000
#define N_ITEMS 150000
#define NNODES  200000
#define NEDGES  1250000
#define DIM     64
#define NLAYERS 3

// scratch: term1 accumulator [N, 64]
__device__ float g_t1[(size_t)NNODES * DIM];

__device__ __forceinline__ void red_add_v4(float* addr, float x, float y, float z, float w) {
    asm volatile("red.global.add.v4.f32 [%0], {%1,%2,%3,%4};"
                 :: "l"(addr), "f"(x), "f"(y), "f"(z), "f"(w) : "memory");
}

// e_0 = concat(user_emb, item_emb) written into out column-block 0
__global__ void init_kernel(const float4* __restrict__ u4, const float4* __restrict__ i4,
                            float4* __restrict__ out4) {
    int i = blockIdx.x * blockDim.x + threadIdx.x;
    if (i >= NNODES * 16) return;
    int row = i >> 4, q = i & 15;
    float4 v = (row < N_USERS) ? u4[row * 16 + q] : i4[(row - N_USERS) * 16 + q];
    out4[(size_t)row * 64 + q] = v;
}

__global__ void zero_t1_kernel() {
    int i = blockIdx.x * blockDim.x + threadIdx.x;
    if (i < NNODES * 16) ((float4*)g_t1)[i] = make_float4(0.f, 0.f, 0.f, 0.f);
}

// term1[dst] += w * e[src]; e read from out column-block `layer`
__global__ void scatter_kernel(const int* __restrict__ src, const int* __restrict__ dst,
                               const float* __restrict__ w, const float4* __restrict__ out4,
                               int layer) {
    int tid = blockIdx.x * blockDim.x + threadIdx.x;
    int edge = tid >> 4;
    if (edge >= NEDGES) return;
    int q = tid & 15;
    int s = src[edge], d = dst[edge];
    float wt = w[edge];
    float4 v = out4[(size_t)s * 64 + layer * 16 + q];
    red_add_v4(&g_t1[((size_t)d * 16 + q) * 4], v.x * wt, v.y * wt, v.z * wt, v.w * wt);
}

// Fused: inter = t1@W0 + (t1*e)@W1 + e@W2 + (b0+b1+b2); leaky_relu; L2-normalize rows.
// Writes e_{l+1} into out column-block layer+1.
// Block tile: 128 rows x 64 cols (full width). 256 threads; thread tile 8 rows x 4 cols.
#define GEMM_BM 128
#define GEMM_SMEM_FLOATS (2 * GEMM_BM * 64 + 3 * 64 * 64 + 64)
#define GEMM_SMEM_BYTES  (GEMM_SMEM_FLOATS * 4)

__global__ __launch_bounds__(256, 2)
void gemm_kernel(const float* __restrict__ Ws, const float* __restrict__ bs,
                 float4* __restrict__ out4, int layer) {
    extern __shared__ float sm[];
    float* sA1 = sm;                  // [128][64] term1 tile
    float* sA3 = sm + GEMM_BM * 64;   // [128][64] e tile
    float* sW  = sm + 2 * GEMM_BM * 64;          // 3 x [64][64]
    float* sB  = sW + 3 * 64 * 64;               // [64] combined bias

    const int tid  = threadIdx.x;
    const int row0 = blockIdx.x * GEMM_BM;

    // stage W (straight copy, k-major rows)
    {
        const float4* Wg = (const float4*)(Ws + (size_t)layer * 3 * 64 * 64);
        float4* sW4 = (float4*)sW;
        #pragma unroll
        for (int i = tid; i < 3 * 64 * 16; i += 256) sW4[i] = Wg[i];
    }
    if (tid < 64) {
        const float* bg = bs + layer * 3 * 64;
        sB[tid] = bg[tid] + bg[64 + tid] + bg[128 + tid];
    }
    // stage A tiles (coalesced float4)
    {
        const float4* t14 = (const float4*)g_t1;
        #pragma unroll
        for (int i = tid; i < GEMM_BM * 16; i += 256) {
            int r = i >> 4, q = i & 15;
            int row = row0 + r;
            float4 v1 = make_float4(0.f, 0.f, 0.f, 0.f), v3 = v1;
            if (row < NNODES) {
                v1 = t14[(size_t)row * 16 + q];
                v3 = out4[(size_t)row * 64 + layer * 16 + q];
            }
            ((float4*)(sA1 + r * 64))[q] = v1;
            ((float4*)(sA3 + r * 64))[q] = v3;
        }
    }
    __syncthreads();

    const int col_t = tid & 15;      // 16 col-threads * 4 cols = 64
    const int row_t = tid >> 4;      // 16 row-threads * 8 rows = 128
    const int c0 = col_t * 4;
    const int r0 = row_t * 8;

    float4 acc[8];
    #pragma unroll
    for (int i = 0; i < 8; i++) acc[i] = make_float4(0.f, 0.f, 0.f, 0.f);

    #pragma unroll
    for (int k4 = 0; k4 < 16; k4++) {
        float a1s[8][4], a3s[8][4];
        #pragma unroll
        for (int i = 0; i < 8; i++) {
            float4 t1v = *(const float4*)(sA1 + (r0 + i) * 64 + k4 * 4);
            float4 t3v = *(const float4*)(sA3 + (r0 + i) * 64 + k4 * 4);
            a1s[i][0] = t1v.x; a1s[i][1] = t1v.y; a1s[i][2] = t1v.z; a1s[i][3] = t1v.w;
            a3s[i][0] = t3v.x; a3s[i][1] = t3v.y; a3s[i][2] = t3v.z; a3s[i][3] = t3v.w;
        }
        #pragma unroll
        for (int kk = 0; kk < 4; kk++) {
            int k = k4 * 4 + kk;
            float4 w0 = *(const float4*)(sW + k * 64 + c0);
            float4 w1 = *(const float4*)(sW + 4096 + k * 64 + c0);
            float4 w2 = *(const float4*)(sW + 8192 + k * 64 + c0);
            #pragma unroll
            for (int i = 0; i < 8; i++) {
                float av1 = a1s[i][kk];
                float av3 = a3s[i][kk];
                float av2 = av1 * av3;
                acc[i].x += av1 * w0.x; acc[i].y += av1 * w0.y;
                acc[i].z += av1 * w0.z; acc[i].w += av1 * w0.w;
                acc[i].x += av2 * w1.x; acc[i].y += av2 * w1.y;
                acc[i].z += av2 * w1.z; acc[i].w += av2 * w1.w;
                acc[i].x += av3 * w2.x; acc[i].y += av3 * w2.y;
                acc[i].z += av3 * w2.z; acc[i].w += av3 * w2.w;
            }
        }
    }

    // epilogue: bias + leaky_relu + row L2 norm (rows owned by 16 consecutive lanes)
    float4 bb = *(const float4*)(sB + c0);
    float part[8];
    #pragma unroll
    for (int i = 0; i < 8; i++) {
        float4 v = acc[i];
        v.x += bb.x; v.y += bb.y; v.z += bb.z; v.w += bb.w;
        v.x = (v.x >= 0.f) ? v.x : 0.01f * v.x;
        v.y = (v.y >= 0.f) ? v.y : 0.01f * v.y;
        v.z = (v.z >= 0.f) ? v.z : 0.01f * v.z;
        v.w = (v.w >= 0.f) ? v.w : 0.01f * v.w;
        acc[i] = v;
        part[i] = v.x * v.x + v.y * v.y + v.z * v.z + v.w * v.w;
    }
    #pragma unroll
    for (int m = 1; m < 16; m <<= 1) {
        #pragma unroll
        for (int i = 0; i < 8; i++)
            part[i] += __shfl_xor_sync(0xffffffffu, part[i], m);
    }
    #pragma unroll
    for (int i = 0; i < 8; i++) {
        int row = row0 + r0 + i;
        if (row < NNODES) {
            float nrm = sqrtf(part[i]);
            float inv = 1.0f / fmaxf(nrm, 1e-12f);
            float4 v = acc[i];
            v.x *= inv; v.y *= inv; v.z *= inv; v.w *= inv;
            out4[(size_t)row * 64 + (layer + 1) * 16 + col_t] = v;
        }
    }
}

extern "C" void kernel_launch(void* const* d_in, const int* in_sizes, int n_in,
                              void* d_out, int out_size) {
    const int*   edge_src = (const int*)d_in[0];
    const int*   edge_dst = (const int*)d_in[1];
    const float* edge_w   = (const float*)d_in[2];
    const float4* u4      = (const float4*)d_in[3];
    const float4* i4      = (const float4*)d_in[4];
    const float* Ws       = (const float*)d_in[5];
    const float* bs       = (const float*)d_in[6];
    float4* out4          = (float4*)d_out;

    cudaFuncSetAttribute(gemm_kernel, cudaFuncAttributeMaxDynamicSharedMemorySize,
                         GEMM_SMEM_BYTES);

    init_kernel<<<(NNODES * 16 + 255) / 256, 256>>>(u4, i4, out4);

    const int gemm_grid = (NNODES + GEMM_BM - 1) / GEMM_BM;
    for (int l = 0; l < NLAYERS; l++) {
        zero_t1_kernel<<<(NNODES * 16 + 255) / 256, 256>>>();
        scatter_kernel<<<(NEDGES * 16 + 255) / 256, 256>>>(edge_src, edge_dst, edge_w, out4, l);
        gemm_kernel<<<gemm_grid, 256, GEMM_SMEM_BYTES>>>(Ws, bs, out4, l);
    }
}